// round 13
// baseline (speedup 1.0000x reference)
#include <cuda_runtime.h>
#include <cuda_bf16.h>
#include <math.h>

// ---------------------------------------------------------------------------
// DeepJ biaxial LSTM.  B=1024, N=48, TU=256, NU=128, IN_T=50 (pad 64).
//   - time-axis layers: single step h=c=0 => feed-forward gate GEMMs on
//     mma.sync m16n8k16 bf16 with 3xK hi/lo split and FUSED activation
//     epilogue emitting the next layer's split-concat bf16 input.
//     N-major block raster for L2 reuse of the A tile.  (R12, known-good.)
//   - note-axis scan: persistent scalar fp32, NOW 512 threads/block
//     (4 warps/SMSP) for latency hiding; 128 blocks x 8 batches,
//     2 batches/thread.  Same smem layout / bank-safe addressing.
// ---------------------------------------------------------------------------

#define BB 1024
#define NN 48
#define MM (BB * NN)   // 49152

typedef __nv_bfloat16 bf16;

// scratch (device globals: allocation-free)
__device__ bf16  g_ac0[MM * 192];      // rnn_in split-concat (K'=192)
__device__ bf16  g_ac1[MM * 768];      // h1 split-concat     (K'=768)
__device__ bf16  g_ac2[MM * 768];      // feats split-concat  (K'=768)
__device__ bf16  g_w0i[768 * 192];     // t_Wih0 live-gate interleaved split-concat
__device__ bf16  g_w1i[768 * 768];     // t_Wih1 live-gate interleaved split-concat
__device__ bf16  g_w2c[512 * 768];     // n_Wih0[:, :256] split-concat (gate-blocked)
__device__ float g_wc[512];            // n_Wih0[:, 256] (cond column)
__device__ float g_xw[MM * 512];       // raw gates for the scan

__device__ __forceinline__ float sigf(float x) { return 1.0f / (1.0f + expf(-x)); }

__device__ __forceinline__ void mma16(float c[4], const unsigned a[4],
                                      const unsigned b[2]) {
    asm volatile(
        "mma.sync.aligned.m16n8k16.row.col.f32.bf16.bf16.f32 "
        "{%0,%1,%2,%3}, {%4,%5,%6,%7}, {%8,%9}, {%0,%1,%2,%3};"
        : "+f"(c[0]), "+f"(c[1]), "+f"(c[2]), "+f"(c[3])
        : "r"(a[0]), "r"(a[1]), "r"(a[2]), "r"(a[3]), "r"(b[0]), "r"(b[1]));
}

// ----------------------------- prep kernels -------------------------------

__device__ __forceinline__ void split3(float v, bf16* p0, bf16* p1, bf16* p2) {
    bf16 hh = __float2bfloat16(v);
    bf16 hl = __float2bfloat16(v - __bfloat162float(hh));
    *p0 = hh; *p1 = hl; *p2 = hh;          // activations: [hi | lo | hi]
}
__device__ __forceinline__ void splitw(float v, bf16* p0, bf16* p1, bf16* p2) {
    bf16 hh = __float2bfloat16(v);
    bf16 hl = __float2bfloat16(v - __bfloat162float(hh));
    *p0 = hh; *p1 = hh; *p2 = hl;          // weights: [hi | hi | lo]
}

__global__ void build_ac0(const float* __restrict__ note) {
    int idx = blockIdx.x * blockDim.x + threadIdx.x;   // MM * 64
    if (idx >= MM * 64) return;
    int f = idx & 63;
    int m = idx >> 6;
    int b = m / NN, n = m % NN;
    float v = 0.0f;
    if (f == 0) {
        v = (float)n * (1.0f / (float)NN);
    } else if (f < 13) {
        v = ((f - 1) == (n % 12)) ? 1.0f : 0.0f;
    } else if (f < 38) {
        int p = n + (f - 13) - 12;
        v = (p >= 0 && p < NN) ? note[b * NN + p] : 0.0f;
    } else if (f < 50) {
        const float* nb = note + b * NN + (f - 38) * 4;
        v = nb[0] + nb[1] + nb[2] + nb[3];
    }
    size_t o = (size_t)m * 192 + f;
    split3(v, &g_ac0[o], &g_ac0[o + 64], &g_ac0[o + 128]);
}

// t_Wih0 (1024 x 50) -> interleaved live gates (row 3u+g3), K pad 64, split x3
__global__ void build_w0i(const float* __restrict__ w) {
    int idx = blockIdx.x * blockDim.x + threadIdx.x;   // 768 * 64
    if (idx >= 768 * 64) return;
    int k = idx & 63, r = idx >> 6;
    int u = r / 3, g3 = r - 3 * u;
    int ga = (g3 == 0) ? 0 : g3 + 1;
    float v = (k < 50) ? w[(size_t)(ga * 256 + u) * 50 + k] : 0.0f;
    size_t o = (size_t)r * 192 + k;
    splitw(v, &g_w0i[o], &g_w0i[o + 64], &g_w0i[o + 128]);
}

// t_Wih1 (1024 x 256) -> interleaved live gates, K'=768
__global__ void build_w1i(const float* __restrict__ w) {
    int idx = blockIdx.x * blockDim.x + threadIdx.x;   // 768 * 256
    if (idx >= 768 * 256) return;
    int k = idx & 255, r = idx >> 8;
    int u = r / 3, g3 = r - 3 * u;
    int ga = (g3 == 0) ? 0 : g3 + 1;
    float v = w[(size_t)(ga * 256 + u) * 256 + k];
    size_t o = (size_t)r * 768 + k;
    splitw(v, &g_w1i[o], &g_w1i[o + 256], &g_w1i[o + 512]);
}

// n_Wih0 (512 x 257) gate-blocked -> split-concat K'=768 ; extracts cond col
__global__ void build_w2c(const float* __restrict__ w) {
    int idx = blockIdx.x * blockDim.x + threadIdx.x;   // 512 * 256
    if (idx >= 512 * 256) return;
    int k = idx & 255, r = idx >> 8;
    float v = w[(size_t)r * 257 + k];
    size_t o = (size_t)r * 768 + k;
    splitw(v, &g_w2c[o], &g_w2c[o + 256], &g_w2c[o + 512]);
    if (k == 0) g_wc[r] = w[(size_t)r * 257 + 256];
}

// ------------------ bf16 mma.sync gate GEMM, fused activation --------------
// (verbatim from the 2011us best)

template <int NT, int NI, bool ACT>
__global__ __launch_bounds__(256)
void gemm_bfa(const bf16* __restrict__ A, int Kp,
              const bf16* __restrict__ W,
              const float* __restrict__ bias,
              bf16* __restrict__ outb_, float* __restrict__ outf) {
    extern __shared__ char smem[];
    bf16* sA = (bf16*)smem;                       // [128][40]
    bf16* sB = (bf16*)(smem + 128 * 40 * 2);      // [NT][40]

    const int t = threadIdx.x;
    const int lane = t & 31, wid = t >> 5;
    const int wm = wid & 3, wn = wid >> 2;
    const int gid = lane >> 2, tid4 = lane & 3;
    const int m0 = blockIdx.y * 128;
    const int c0 = blockIdx.x * NT;

    float acc[2][NI][4];
#pragma unroll
    for (int mi = 0; mi < 2; mi++)
#pragma unroll
        for (int ni = 0; ni < NI; ni++)
#pragma unroll
            for (int q = 0; q < 4; q++) acc[mi][ni][q] = 0.0f;

    const int ar = t >> 2, ap = (t & 3) * 8;
    int  br[2]; bool bval[2];
#pragma unroll
    for (int j = 0; j < 2; j++) {
        int lin = t + 256 * j;
        bval[j] = (lin < NT * 4);
        br[j] = bval[j] ? lin : 0;
    }

    uint4 pa0, pa1, pb[2];
    pa0 = *(const uint4*)(A + (size_t)(m0 + ar) * Kp + ap);
    pa1 = *(const uint4*)(A + (size_t)(m0 + ar + 64) * Kp + ap);
#pragma unroll
    for (int j = 0; j < 2; j++)
        if (bval[j])
            pb[j] = *(const uint4*)(W + (size_t)(c0 + (br[j] >> 2)) * Kp
                                      + (br[j] & 3) * 8);

    const int nchunks = Kp >> 5;
    for (int kc = 0; kc < nchunks; kc++) {
        *(uint4*)&sA[ar * 40 + ap]        = pa0;
        *(uint4*)&sA[(ar + 64) * 40 + ap] = pa1;
#pragma unroll
        for (int j = 0; j < 2; j++)
            if (bval[j])
                *(uint4*)&sB[(br[j] >> 2) * 40 + (br[j] & 3) * 8] = pb[j];
        __syncthreads();

        if (kc + 1 < nchunks) {
            int ko = (kc + 1) * 32;
            pa0 = *(const uint4*)(A + (size_t)(m0 + ar) * Kp + ko + ap);
            pa1 = *(const uint4*)(A + (size_t)(m0 + ar + 64) * Kp + ko + ap);
#pragma unroll
            for (int j = 0; j < 2; j++)
                if (bval[j])
                    pb[j] = *(const uint4*)(W + (size_t)(c0 + (br[j] >> 2)) * Kp
                                              + ko + (br[j] & 3) * 8);
        }

#pragma unroll
        for (int kh = 0; kh < 2; kh++) {
            const int kb = kh * 16;
            unsigned Af[2][4], Bf[NI][2];
#pragma unroll
            for (int mi = 0; mi < 2; mi++) {
                int r = wm * 32 + mi * 16 + gid;
                Af[mi][0] = *(const unsigned*)&sA[r * 40 + kb + tid4 * 2];
                Af[mi][1] = *(const unsigned*)&sA[(r + 8) * 40 + kb + tid4 * 2];
                Af[mi][2] = *(const unsigned*)&sA[r * 40 + kb + tid4 * 2 + 8];
                Af[mi][3] = *(const unsigned*)&sA[(r + 8) * 40 + kb + tid4 * 2 + 8];
            }
#pragma unroll
            for (int ni = 0; ni < NI; ni++) {
                int c = wn * (NT / 2) + ni * 8 + gid;
                Bf[ni][0] = *(const unsigned*)&sB[c * 40 + kb + tid4 * 2];
                Bf[ni][1] = *(const unsigned*)&sB[c * 40 + kb + tid4 * 2 + 8];
            }
#pragma unroll
            for (int mi = 0; mi < 2; mi++)
#pragma unroll
                for (int ni = 0; ni < NI; ni++)
                    mma16(acc[mi][ni], Af[mi], Bf[ni]);
        }
        __syncthreads();
    }

    float* sd = (float*)smem;
    const int NTS = NT + 4;
#pragma unroll
    for (int mi = 0; mi < 2; mi++)
#pragma unroll
        for (int ni = 0; ni < NI; ni++) {
            int r = wm * 32 + mi * 16 + gid;
            int c = wn * (NT / 2) + ni * 8 + tid4 * 2;
            sd[r * NTS + c]           = acc[mi][ni][0];
            sd[r * NTS + c + 1]       = acc[mi][ni][1];
            sd[(r + 8) * NTS + c]     = acc[mi][ni][2];
            sd[(r + 8) * NTS + c + 1] = acc[mi][ni][3];
        }
    __syncthreads();

    if constexpr (ACT) {
        const int ul = t & 31, mr = t >> 5;
        const int ug = blockIdx.x * 32 + ul;
        const float bi = bias[ug];
        const float bg = bias[2 * 256 + ug];
        const float bo = bias[3 * 256 + ug];
#pragma unroll
        for (int j = 0; j < 16; j++) {
            int m = mr + j * 8;
            float gi = sd[m * NTS + ul * 3 + 0] + bi;
            float gg = sd[m * NTS + ul * 3 + 1] + bg;
            float go = sd[m * NTS + ul * 3 + 2] + bo;
            float h = sigf(go) * tanhf(sigf(gi) * tanhf(gg));
            size_t o = (size_t)(m0 + m) * 768 + ug;
            split3(h, &outb_[o], &outb_[o + 256], &outb_[o + 512]);
        }
    } else {
#pragma unroll
        for (int j = 0; j < 16; j++) {
            int i = j * 256 + t;
            int r = i >> 5, c4 = i & 31;
            *(float4*)&outf[(size_t)(m0 + r) * 512 + c0 + c4 * 4] =
                *(float4*)&sd[r * NTS + c4 * 4];
        }
    }
}

// ------------------------------ note-axis scan -----------------------------
// 512 threads (4 warps/SMSP), 128 blocks x 8 batches, 2 batches/thread.
// Weights staged per 16-k tile into double-buffered shared (pad-20 stride).

__device__ __forceinline__ void load_wtile_regs(float4 pre[4],
                                                const float* __restrict__ W,
                                                int kt, int t) {
#pragma unroll
    for (int i = 0; i < 4; i++) {
        int lin = t + 512 * i;          // 512 rows x 4 float4 = 2048
        int r = lin >> 2, k4 = lin & 3;
        pre[i] = *(const float4*)&W[r * 128 + kt + k4 * 4];
    }
}

__device__ __forceinline__ void sts_wtile(float* dst, const float4 pre[4], int t) {
#pragma unroll
    for (int i = 0; i < 4; i++) {
        int lin = t + 512 * i;
        int r = lin >> 2, k4 = lin & 3;
        *(float4*)&dst[r * 20 + k4 * 4] = pre[i];
    }
}

__device__ __forceinline__ void accum_tile(float acc[2][4], const float* sWt,
                                           const float* sH, int kt, int u, int bp) {
#pragma unroll
    for (int kk = 0; kk < 16; kk += 4) {
        float4 wv[4];
#pragma unroll
        for (int g = 0; g < 4; g++)
            wv[g] = *(const float4*)&sWt[(g * 128 + u) * 20 + kk];
#pragma unroll
        for (int b = 0; b < 2; b++) {
            float4 hv = *(const float4*)&sH[(bp * 2 + b) * 128 + kt + kk];
#pragma unroll
            for (int g = 0; g < 4; g++) {
                acc[b][g] += hv.x * wv[g].x;
                acc[b][g] += hv.y * wv[g].y;
                acc[b][g] += hv.z * wv[g].z;
                acc[b][g] += hv.w * wv[g].w;
            }
        }
    }
}

__device__ __forceinline__ void gemm_pass(float acc[2][4],
                                          const float* __restrict__ W,
                                          const float* sH, float* sW,
                                          int t, int u, int bp) {
    float4 pre[4];
    load_wtile_regs(pre, W, 0, t);
    sts_wtile(sW, pre, t);
    __syncthreads();
    for (int it = 0; it < 8; it++) {
        float* cur = sW + (it & 1) * 10240;
        if (it < 7) load_wtile_regs(pre, W, (it + 1) * 16, t);
        accum_tile(acc, cur, sH, it * 16, u, bp);
        if (it < 7) sts_wtile(sW + ((it + 1) & 1) * 10240, pre, t);
        __syncthreads();
    }
}

__global__ __launch_bounds__(512, 1)
void scan_kernel(const float* __restrict__ targets,
                 const float* __restrict__ Whh0,
                 const float* __restrict__ nb0,
                 const float* __restrict__ Wih1,
                 const float* __restrict__ Whh1,
                 const float* __restrict__ nb1,
                 const float* __restrict__ outW,
                 const float* __restrict__ outb,
                 float* __restrict__ out) {
    extern __shared__ float sh[];
    float* sW  = sh;              // 2 x 512 x 20 = 20480
    float* sH1 = sh + 20480;      // 8 x 128
    float* sH2 = sH1 + 1024;      // 8 x 128
    float* sWo = sH2 + 1024;      // 128

    const int t = threadIdx.x;
    const int u = t & 127, bp = t >> 7;       // bp in 0..3, 2 batches each
    const int B0 = blockIdx.x * 8;

    if (t < 128) sWo[t] = outW[t];
    for (int i = t; i < 2048; i += 512) sH1[i] = 0.0f;  // zeros sH1+sH2

    float c1[2] = {0, 0}, c2[2] = {0, 0};
    float b0r[4], b1r[4], wcr[4];
#pragma unroll
    for (int g = 0; g < 4; g++) {
        b0r[g] = nb0[g * 128 + u];
        b1r[g] = nb1[g * 128 + u];
        wcr[g] = g_wc[g * 128 + u];
    }
    const float ob = outb[0];
    __syncthreads();

    for (int n = 0; n < NN; n++) {
        // ---- layer 0 ----
        float acc[2][4];
#pragma unroll
        for (int b = 0; b < 2; b++) {
            int bg = B0 + bp * 2 + b;
            float cond = (n == 0) ? 0.0f : targets[bg * NN + n - 1];
            size_t m = (size_t)bg * NN + n;
#pragma unroll
            for (int g = 0; g < 4; g++)
                acc[b][g] = g_xw[m * 512 + g * 128 + u] + b0r[g] + cond * wcr[g];
        }
        gemm_pass(acc, Whh0, sH1, sW, t, u, bp);

        float h1n[2];
#pragma unroll
        for (int b = 0; b < 2; b++) {
            float cc = sigf(acc[b][1]) * c1[b] + sigf(acc[b][0]) * tanhf(acc[b][2]);
            c1[b] = cc;
            h1n[b] = sigf(acc[b][3]) * tanhf(cc);
        }
#pragma unroll
        for (int b = 0; b < 2; b++) sH1[(bp * 2 + b) * 128 + u] = h1n[b];
        __syncthreads();

        // ---- layer 1 ----
        float acc2[2][4];
#pragma unroll
        for (int b = 0; b < 2; b++)
#pragma unroll
            for (int g = 0; g < 4; g++) acc2[b][g] = b1r[g];
        gemm_pass(acc2, Wih1, sH1, sW, t, u, bp);
        gemm_pass(acc2, Whh1, sH2, sW, t, u, bp);

        float h2n[2];
#pragma unroll
        for (int b = 0; b < 2; b++) {
            float cc = sigf(acc2[b][1]) * c2[b] + sigf(acc2[b][0]) * tanhf(acc2[b][2]);
            c2[b] = cc;
            h2n[b] = sigf(acc2[b][3]) * tanhf(cc);
        }
#pragma unroll
        for (int b = 0; b < 2; b++) sH2[(bp * 2 + b) * 128 + u] = h2n[b];
        __syncthreads();

        // ---- output: warps 0..7 -> batch w; warps 8..15 idle ----
        int w = t >> 5, lane = t & 31;
        if (w < 8) {
            float p = 0.0f;
#pragma unroll
            for (int j = 0; j < 4; j++)
                p += sH2[w * 128 + lane + 32 * j] * sWo[lane + 32 * j];
#pragma unroll
            for (int off = 16; off; off >>= 1)
                p += __shfl_down_sync(0xffffffffu, p, off);
            if (lane == 0) out[(B0 + w) * NN + n] = sigf(p + ob);
        }
        // sH2 next rewritten only after layer-1 passes (internal barriers)
    }
}

// --------------------------------- launch ---------------------------------

extern "C" void kernel_launch(void* const* d_in, const int* in_sizes, int n_in,
                              void* d_out, int out_size) {
    (void)in_sizes; (void)n_in; (void)out_size;
    const float* note    = (const float*)d_in[0];
    const float* targets = (const float*)d_in[1];
    const float* tWih0   = (const float*)d_in[2];
    const float* tb0     = (const float*)d_in[4];
    const float* tWih1   = (const float*)d_in[5];
    const float* tb1     = (const float*)d_in[7];
    const float* nWih0   = (const float*)d_in[8];
    const float* nWhh0   = (const float*)d_in[9];
    const float* nb0     = (const float*)d_in[10];
    const float* nWih1   = (const float*)d_in[11];
    const float* nWhh1   = (const float*)d_in[12];
    const float* nb1     = (const float*)d_in[13];
    const float* outW    = (const float*)d_in[14];
    const float* outb    = (const float*)d_in[15];
    float* out = (float*)d_out;

    bf16 *p_ac0, *p_ac1, *p_ac2, *p_w0i, *p_w1i, *p_w2c;
    float *p_xw;
    cudaGetSymbolAddress((void**)&p_ac0, g_ac0);
    cudaGetSymbolAddress((void**)&p_ac1, g_ac1);
    cudaGetSymbolAddress((void**)&p_ac2, g_ac2);
    cudaGetSymbolAddress((void**)&p_w0i, g_w0i);
    cudaGetSymbolAddress((void**)&p_w1i, g_w1i);
    cudaGetSymbolAddress((void**)&p_w2c, g_w2c);
    cudaGetSymbolAddress((void**)&p_xw,  g_xw);

    build_ac0<<<(MM * 64) / 256, 256>>>(note);
    build_w0i<<<(768 * 64) / 256, 256>>>(tWih0);
    build_w1i<<<(768 * 256) / 256, 256>>>(tWih1);
    build_w2c<<<(512 * 256) / 256, 256>>>(nWih0);

    const int smemA = 128 * 100 * (int)sizeof(float);   // 51200
    const int smemR = 128 * 132 * (int)sizeof(float);   // 67584
    cudaFuncSetAttribute((const void*)gemm_bfa<96, 6, true>,
                         cudaFuncAttributeMaxDynamicSharedMemorySize, smemA);
    cudaFuncSetAttribute((const void*)gemm_bfa<128, 8, false>,
                         cudaFuncAttributeMaxDynamicSharedMemorySize, smemR);

    // h1 = act(rnn_in' @ w0i'^T + b0)        (K'=192)
    gemm_bfa<96, 6, true><<<dim3(8, 384), 256, smemA>>>(p_ac0, 192, p_w0i,
                                                        tb0, p_ac1, nullptr);
    // feats = act(h1' @ w1i'^T + b1)         (K'=768)
    gemm_bfa<96, 6, true><<<dim3(8, 384), 256, smemA>>>(p_ac1, 768, p_w1i,
                                                        tb1, p_ac2, nullptr);
    // g_xw = feats' @ w2c'^T                 (K'=768, raw gates for the scan)
    gemm_bfa<128, 8, false><<<dim3(4, 384), 256, smemR>>>(p_ac2, 768, p_w2c,
                                                          nullptr, nullptr, p_xw);

    const int smemS = 22656 * (int)sizeof(float);  // 90624 B
    cudaFuncSetAttribute(scan_kernel, cudaFuncAttributeMaxDynamicSharedMemorySize, smemS);
    scan_kernel<<<128, 512, smemS>>>(targets, nWhh0, nb0, nWih1, nWhh1, nb1,
                                     outW, outb, out);
}

// round 14
// speedup vs baseline: 1.2197x; 1.2197x over previous
#include <cuda_runtime.h>
#include <cuda_bf16.h>
#include <math.h>

// ---------------------------------------------------------------------------
// DeepJ biaxial LSTM.  B=1024, N=48, TU=256, NU=128, IN_T=50 (pad 64).
//   - time-axis layers: single step h=c=0 => feed-forward gate GEMMs on
//     mma.sync m16n8k16 bf16 with 3xK hi/lo split and FUSED activation
//     epilogue emitting the next layer's split-concat bf16 input.
//     N-major block raster for L2 reuse of the A tile.  (R12, known-good.)
//   - note-axis scan: persistent scalar fp32, 256 threads, 128 blocks x 8
//     batches (R12 structure).  NEW: weight staging via cp.async 3-buffer
//     ring (no register round-trip, one barrier/tile); sigmoid via __expf.
// ---------------------------------------------------------------------------

#define BB 1024
#define NN 48
#define MM (BB * NN)   // 49152

typedef __nv_bfloat16 bf16;

// scratch (device globals: allocation-free)
__device__ bf16  g_ac0[MM * 192];      // rnn_in split-concat (K'=192)
__device__ bf16  g_ac1[MM * 768];      // h1 split-concat     (K'=768)
__device__ bf16  g_ac2[MM * 768];      // feats split-concat  (K'=768)
__device__ bf16  g_w0i[768 * 192];     // t_Wih0 live-gate interleaved split-concat
__device__ bf16  g_w1i[768 * 768];     // t_Wih1 live-gate interleaved split-concat
__device__ bf16  g_w2c[512 * 768];     // n_Wih0[:, :256] split-concat (gate-blocked)
__device__ float g_wc[512];            // n_Wih0[:, 256] (cond column)
__device__ float g_xw[MM * 512];       // raw gates for the scan

__device__ __forceinline__ float sigf(float x) {
    return __fdividef(1.0f, 1.0f + __expf(-x));
}

__device__ __forceinline__ void mma16(float c[4], const unsigned a[4],
                                      const unsigned b[2]) {
    asm volatile(
        "mma.sync.aligned.m16n8k16.row.col.f32.bf16.bf16.f32 "
        "{%0,%1,%2,%3}, {%4,%5,%6,%7}, {%8,%9}, {%0,%1,%2,%3};"
        : "+f"(c[0]), "+f"(c[1]), "+f"(c[2]), "+f"(c[3])
        : "r"(a[0]), "r"(a[1]), "r"(a[2]), "r"(a[3]), "r"(b[0]), "r"(b[1]));
}

static __device__ __forceinline__ unsigned smem_u32(const void* p) {
    unsigned a;
    asm("{ .reg .u64 t; cvta.to.shared.u64 t, %1; cvt.u32.u64 %0, t; }"
        : "=r"(a) : "l"(p));
    return a;
}
__device__ __forceinline__ void cp16(unsigned dst, const void* src) {
    asm volatile("cp.async.cg.shared.global [%0], [%1], 16;"
                 :: "r"(dst), "l"(src) : "memory");
}
template <int N>
__device__ __forceinline__ void cpwait() {
    asm volatile("cp.async.wait_group %0;" :: "n"(N) : "memory");
}

// ----------------------------- prep kernels -------------------------------

__device__ __forceinline__ void split3(float v, bf16* p0, bf16* p1, bf16* p2) {
    bf16 hh = __float2bfloat16(v);
    bf16 hl = __float2bfloat16(v - __bfloat162float(hh));
    *p0 = hh; *p1 = hl; *p2 = hh;          // activations: [hi | lo | hi]
}
__device__ __forceinline__ void splitw(float v, bf16* p0, bf16* p1, bf16* p2) {
    bf16 hh = __float2bfloat16(v);
    bf16 hl = __float2bfloat16(v - __bfloat162float(hh));
    *p0 = hh; *p1 = hh; *p2 = hl;          // weights: [hi | hi | lo]
}

__global__ void build_ac0(const float* __restrict__ note) {
    int idx = blockIdx.x * blockDim.x + threadIdx.x;   // MM * 64
    if (idx >= MM * 64) return;
    int f = idx & 63;
    int m = idx >> 6;
    int b = m / NN, n = m % NN;
    float v = 0.0f;
    if (f == 0) {
        v = (float)n * (1.0f / (float)NN);
    } else if (f < 13) {
        v = ((f - 1) == (n % 12)) ? 1.0f : 0.0f;
    } else if (f < 38) {
        int p = n + (f - 13) - 12;
        v = (p >= 0 && p < NN) ? note[b * NN + p] : 0.0f;
    } else if (f < 50) {
        const float* nb = note + b * NN + (f - 38) * 4;
        v = nb[0] + nb[1] + nb[2] + nb[3];
    }
    size_t o = (size_t)m * 192 + f;
    split3(v, &g_ac0[o], &g_ac0[o + 64], &g_ac0[o + 128]);
}

// t_Wih0 (1024 x 50) -> interleaved live gates (row 3u+g3), K pad 64, split x3
__global__ void build_w0i(const float* __restrict__ w) {
    int idx = blockIdx.x * blockDim.x + threadIdx.x;   // 768 * 64
    if (idx >= 768 * 64) return;
    int k = idx & 63, r = idx >> 6;
    int u = r / 3, g3 = r - 3 * u;
    int ga = (g3 == 0) ? 0 : g3 + 1;
    float v = (k < 50) ? w[(size_t)(ga * 256 + u) * 50 + k] : 0.0f;
    size_t o = (size_t)r * 192 + k;
    splitw(v, &g_w0i[o], &g_w0i[o + 64], &g_w0i[o + 128]);
}

// t_Wih1 (1024 x 256) -> interleaved live gates, K'=768
__global__ void build_w1i(const float* __restrict__ w) {
    int idx = blockIdx.x * blockDim.x + threadIdx.x;   // 768 * 256
    if (idx >= 768 * 256) return;
    int k = idx & 255, r = idx >> 8;
    int u = r / 3, g3 = r - 3 * u;
    int ga = (g3 == 0) ? 0 : g3 + 1;
    float v = w[(size_t)(ga * 256 + u) * 256 + k];
    size_t o = (size_t)r * 768 + k;
    splitw(v, &g_w1i[o], &g_w1i[o + 256], &g_w1i[o + 512]);
}

// n_Wih0 (512 x 257) gate-blocked -> split-concat K'=768 ; extracts cond col
__global__ void build_w2c(const float* __restrict__ w) {
    int idx = blockIdx.x * blockDim.x + threadIdx.x;   // 512 * 256
    if (idx >= 512 * 256) return;
    int k = idx & 255, r = idx >> 8;
    float v = w[(size_t)r * 257 + k];
    size_t o = (size_t)r * 768 + k;
    splitw(v, &g_w2c[o], &g_w2c[o + 256], &g_w2c[o + 512]);
    if (k == 0) g_wc[r] = w[(size_t)r * 257 + 256];
}

// ------------------ bf16 mma.sync gate GEMM, fused activation --------------
// (verbatim from the 2011us best, sigf now __expf-based)

template <int NT, int NI, bool ACT>
__global__ __launch_bounds__(256)
void gemm_bfa(const bf16* __restrict__ A, int Kp,
              const bf16* __restrict__ W,
              const float* __restrict__ bias,
              bf16* __restrict__ outb_, float* __restrict__ outf) {
    extern __shared__ char smem[];
    bf16* sA = (bf16*)smem;                       // [128][40]
    bf16* sB = (bf16*)(smem + 128 * 40 * 2);      // [NT][40]

    const int t = threadIdx.x;
    const int lane = t & 31, wid = t >> 5;
    const int wm = wid & 3, wn = wid >> 2;
    const int gid = lane >> 2, tid4 = lane & 3;
    const int m0 = blockIdx.y * 128;
    const int c0 = blockIdx.x * NT;

    float acc[2][NI][4];
#pragma unroll
    for (int mi = 0; mi < 2; mi++)
#pragma unroll
        for (int ni = 0; ni < NI; ni++)
#pragma unroll
            for (int q = 0; q < 4; q++) acc[mi][ni][q] = 0.0f;

    const int ar = t >> 2, ap = (t & 3) * 8;
    int  br[2]; bool bval[2];
#pragma unroll
    for (int j = 0; j < 2; j++) {
        int lin = t + 256 * j;
        bval[j] = (lin < NT * 4);
        br[j] = bval[j] ? lin : 0;
    }

    uint4 pa0, pa1, pb[2];
    pa0 = *(const uint4*)(A + (size_t)(m0 + ar) * Kp + ap);
    pa1 = *(const uint4*)(A + (size_t)(m0 + ar + 64) * Kp + ap);
#pragma unroll
    for (int j = 0; j < 2; j++)
        if (bval[j])
            pb[j] = *(const uint4*)(W + (size_t)(c0 + (br[j] >> 2)) * Kp
                                      + (br[j] & 3) * 8);

    const int nchunks = Kp >> 5;
    for (int kc = 0; kc < nchunks; kc++) {
        *(uint4*)&sA[ar * 40 + ap]        = pa0;
        *(uint4*)&sA[(ar + 64) * 40 + ap] = pa1;
#pragma unroll
        for (int j = 0; j < 2; j++)
            if (bval[j])
                *(uint4*)&sB[(br[j] >> 2) * 40 + (br[j] & 3) * 8] = pb[j];
        __syncthreads();

        if (kc + 1 < nchunks) {
            int ko = (kc + 1) * 32;
            pa0 = *(const uint4*)(A + (size_t)(m0 + ar) * Kp + ko + ap);
            pa1 = *(const uint4*)(A + (size_t)(m0 + ar + 64) * Kp + ko + ap);
#pragma unroll
            for (int j = 0; j < 2; j++)
                if (bval[j])
                    pb[j] = *(const uint4*)(W + (size_t)(c0 + (br[j] >> 2)) * Kp
                                              + ko + (br[j] & 3) * 8);
        }

#pragma unroll
        for (int kh = 0; kh < 2; kh++) {
            const int kb = kh * 16;
            unsigned Af[2][4], Bf[NI][2];
#pragma unroll
            for (int mi = 0; mi < 2; mi++) {
                int r = wm * 32 + mi * 16 + gid;
                Af[mi][0] = *(const unsigned*)&sA[r * 40 + kb + tid4 * 2];
                Af[mi][1] = *(const unsigned*)&sA[(r + 8) * 40 + kb + tid4 * 2];
                Af[mi][2] = *(const unsigned*)&sA[r * 40 + kb + tid4 * 2 + 8];
                Af[mi][3] = *(const unsigned*)&sA[(r + 8) * 40 + kb + tid4 * 2 + 8];
            }
#pragma unroll
            for (int ni = 0; ni < NI; ni++) {
                int c = wn * (NT / 2) + ni * 8 + gid;
                Bf[ni][0] = *(const unsigned*)&sB[c * 40 + kb + tid4 * 2];
                Bf[ni][1] = *(const unsigned*)&sB[c * 40 + kb + tid4 * 2 + 8];
            }
#pragma unroll
            for (int mi = 0; mi < 2; mi++)
#pragma unroll
                for (int ni = 0; ni < NI; ni++)
                    mma16(acc[mi][ni], Af[mi], Bf[ni]);
        }
        __syncthreads();
    }

    float* sd = (float*)smem;
    const int NTS = NT + 4;
#pragma unroll
    for (int mi = 0; mi < 2; mi++)
#pragma unroll
        for (int ni = 0; ni < NI; ni++) {
            int r = wm * 32 + mi * 16 + gid;
            int c = wn * (NT / 2) + ni * 8 + tid4 * 2;
            sd[r * NTS + c]           = acc[mi][ni][0];
            sd[r * NTS + c + 1]       = acc[mi][ni][1];
            sd[(r + 8) * NTS + c]     = acc[mi][ni][2];
            sd[(r + 8) * NTS + c + 1] = acc[mi][ni][3];
        }
    __syncthreads();

    if constexpr (ACT) {
        const int ul = t & 31, mr = t >> 5;
        const int ug = blockIdx.x * 32 + ul;
        const float bi = bias[ug];
        const float bg = bias[2 * 256 + ug];
        const float bo = bias[3 * 256 + ug];
#pragma unroll
        for (int j = 0; j < 16; j++) {
            int m = mr + j * 8;
            float gi = sd[m * NTS + ul * 3 + 0] + bi;
            float gg = sd[m * NTS + ul * 3 + 1] + bg;
            float go = sd[m * NTS + ul * 3 + 2] + bo;
            float h = sigf(go) * tanhf(sigf(gi) * tanhf(gg));
            size_t o = (size_t)(m0 + m) * 768 + ug;
            split3(h, &outb_[o], &outb_[o + 256], &outb_[o + 512]);
        }
    } else {
#pragma unroll
        for (int j = 0; j < 16; j++) {
            int i = j * 256 + t;
            int r = i >> 5, c4 = i & 31;
            *(float4*)&outf[(size_t)(m0 + r) * 512 + c0 + c4 * 4] =
                *(float4*)&sd[r * NTS + c4 * 4];
        }
    }
}

// ------------------------------ note-axis scan -----------------------------
// 256 threads, 128 blocks x 8 batches, 4 batches/thread (R12 structure).
// Weights staged via cp.async 3-buffer ring: one barrier per tile, no
// register round-trip for the weight stream.

__device__ __forceinline__ void issue_tile(const float* __restrict__ W,
                                           int kt, unsigned dst_u32, int t) {
#pragma unroll
    for (int i = 0; i < 8; i++) {
        int lin = t + 256 * i;          // 512 rows x 4 float4
        int r = lin >> 2, k4 = lin & 3;
        cp16(dst_u32 + (unsigned)(r * 80 + k4 * 16),
             W + r * 128 + kt + k4 * 4);
    }
    asm volatile("cp.async.commit_group;" ::: "memory");
}

__device__ __forceinline__ void accum_tile(float acc[4][4], const float* sWt,
                                           const float* sH, int kt, int u, int bp) {
#pragma unroll
    for (int kk = 0; kk < 16; kk += 4) {
        float4 wv[4];
#pragma unroll
        for (int g = 0; g < 4; g++)
            wv[g] = *(const float4*)&sWt[(g * 128 + u) * 20 + kk];
#pragma unroll
        for (int b = 0; b < 4; b++) {
            float4 hv = *(const float4*)&sH[(bp * 4 + b) * 128 + kt + kk];
#pragma unroll
            for (int g = 0; g < 4; g++) {
                acc[b][g] += hv.x * wv[g].x;
                acc[b][g] += hv.y * wv[g].y;
                acc[b][g] += hv.z * wv[g].z;
                acc[b][g] += hv.w * wv[g].w;
            }
        }
    }
}

__device__ __forceinline__ void gemm_pass(float acc[4][4],
                                          const float* __restrict__ W,
                                          const float* sH, float* sW,
                                          unsigned sW_u32,
                                          int t, int u, int bp) {
    issue_tile(W, 0, sW_u32, t);
    issue_tile(W, 16, sW_u32 + 40960, t);
    for (int it = 0; it < 8; it++) {
        if (it < 7) cpwait<1>(); else cpwait<0>();
        __syncthreads();
        if (it + 2 < 8)
            issue_tile(W, (it + 2) * 16, sW_u32 + ((it + 2) % 3) * 40960, t);
        accum_tile(acc, sW + (it % 3) * 10240, sH, it * 16, u, bp);
    }
    __syncthreads();   // last buffers free before caller reuses sH / sW
}

__global__ __launch_bounds__(256, 1)
void scan_kernel(const float* __restrict__ targets,
                 const float* __restrict__ Whh0,
                 const float* __restrict__ nb0,
                 const float* __restrict__ Wih1,
                 const float* __restrict__ Whh1,
                 const float* __restrict__ nb1,
                 const float* __restrict__ outW,
                 const float* __restrict__ outb,
                 float* __restrict__ out) {
    extern __shared__ float sh[];
    float* sW  = sh;              // 3 x 512 x 20 = 30720
    float* sH1 = sh + 30720;      // 8 x 128
    float* sH2 = sH1 + 1024;      // 8 x 128
    float* sWo = sH2 + 1024;      // 128
    const unsigned sW_u32 = smem_u32(sW);

    const int t = threadIdx.x;
    const int u = t & 127, bp = t >> 7;
    const int B0 = blockIdx.x * 8;

    if (t < 128) sWo[t] = outW[t];
    for (int i = t; i < 2048; i += 256) sH1[i] = 0.0f;  // zeros sH1+sH2

    float c1[4] = {0, 0, 0, 0}, c2[4] = {0, 0, 0, 0};
    float b0r[4], b1r[4], wcr[4];
#pragma unroll
    for (int g = 0; g < 4; g++) {
        b0r[g] = nb0[g * 128 + u];
        b1r[g] = nb1[g * 128 + u];
        wcr[g] = g_wc[g * 128 + u];
    }
    const float ob = outb[0];
    __syncthreads();

    for (int n = 0; n < NN; n++) {
        // ---- layer 0 ----
        float acc[4][4];
#pragma unroll
        for (int b = 0; b < 4; b++) {
            int bg = B0 + bp * 4 + b;
            float cond = (n == 0) ? 0.0f : targets[bg * NN + n - 1];
            size_t m = (size_t)bg * NN + n;
#pragma unroll
            for (int g = 0; g < 4; g++)
                acc[b][g] = g_xw[m * 512 + g * 128 + u] + b0r[g] + cond * wcr[g];
        }
        gemm_pass(acc, Whh0, sH1, sW, sW_u32, t, u, bp);

        float h1n[4];
#pragma unroll
        for (int b = 0; b < 4; b++) {
            float cc = sigf(acc[b][1]) * c1[b] + sigf(acc[b][0]) * tanhf(acc[b][2]);
            c1[b] = cc;
            h1n[b] = sigf(acc[b][3]) * tanhf(cc);
        }
#pragma unroll
        for (int b = 0; b < 4; b++) sH1[(bp * 4 + b) * 128 + u] = h1n[b];
        __syncthreads();

        // ---- layer 1 ----
        float acc2[4][4];
#pragma unroll
        for (int b = 0; b < 4; b++)
#pragma unroll
            for (int g = 0; g < 4; g++) acc2[b][g] = b1r[g];
        gemm_pass(acc2, Wih1, sH1, sW, sW_u32, t, u, bp);
        gemm_pass(acc2, Whh1, sH2, sW, sW_u32, t, u, bp);

        float h2n[4];
#pragma unroll
        for (int b = 0; b < 4; b++) {
            float cc = sigf(acc2[b][1]) * c2[b] + sigf(acc2[b][0]) * tanhf(acc2[b][2]);
            c2[b] = cc;
            h2n[b] = sigf(acc2[b][3]) * tanhf(cc);
        }
#pragma unroll
        for (int b = 0; b < 4; b++) sH2[(bp * 4 + b) * 128 + u] = h2n[b];
        __syncthreads();

        // ---- output: warp w handles batch w ----
        int w = t >> 5, lane = t & 31;
        float p = 0.0f;
#pragma unroll
        for (int j = 0; j < 4; j++)
            p += sH2[w * 128 + lane + 32 * j] * sWo[lane + 32 * j];
#pragma unroll
        for (int off = 16; off; off >>= 1)
            p += __shfl_down_sync(0xffffffffu, p, off);
        if (lane == 0) out[(B0 + w) * NN + n] = sigf(p + ob);
    }
}

// --------------------------------- launch ---------------------------------

extern "C" void kernel_launch(void* const* d_in, const int* in_sizes, int n_in,
                              void* d_out, int out_size) {
    (void)in_sizes; (void)n_in; (void)out_size;
    const float* note    = (const float*)d_in[0];
    const float* targets = (const float*)d_in[1];
    const float* tWih0   = (const float*)d_in[2];
    const float* tb0     = (const float*)d_in[4];
    const float* tWih1   = (const float*)d_in[5];
    const float* tb1     = (const float*)d_in[7];
    const float* nWih0   = (const float*)d_in[8];
    const float* nWhh0   = (const float*)d_in[9];
    const float* nb0     = (const float*)d_in[10];
    const float* nWih1   = (const float*)d_in[11];
    const float* nWhh1   = (const float*)d_in[12];
    const float* nb1     = (const float*)d_in[13];
    const float* outW    = (const float*)d_in[14];
    const float* outb    = (const float*)d_in[15];
    float* out = (float*)d_out;

    bf16 *p_ac0, *p_ac1, *p_ac2, *p_w0i, *p_w1i, *p_w2c;
    float *p_xw;
    cudaGetSymbolAddress((void**)&p_ac0, g_ac0);
    cudaGetSymbolAddress((void**)&p_ac1, g_ac1);
    cudaGetSymbolAddress((void**)&p_ac2, g_ac2);
    cudaGetSymbolAddress((void**)&p_w0i, g_w0i);
    cudaGetSymbolAddress((void**)&p_w1i, g_w1i);
    cudaGetSymbolAddress((void**)&p_w2c, g_w2c);
    cudaGetSymbolAddress((void**)&p_xw,  g_xw);

    build_ac0<<<(MM * 64) / 256, 256>>>(note);
    build_w0i<<<(768 * 64) / 256, 256>>>(tWih0);
    build_w1i<<<(768 * 256) / 256, 256>>>(tWih1);
    build_w2c<<<(512 * 256) / 256, 256>>>(nWih0);

    const int smemA = 128 * 100 * (int)sizeof(float);   // 51200
    const int smemR = 128 * 132 * (int)sizeof(float);   // 67584
    cudaFuncSetAttribute((const void*)gemm_bfa<96, 6, true>,
                         cudaFuncAttributeMaxDynamicSharedMemorySize, smemA);
    cudaFuncSetAttribute((const void*)gemm_bfa<128, 8, false>,
                         cudaFuncAttributeMaxDynamicSharedMemorySize, smemR);

    // h1 = act(rnn_in' @ w0i'^T + b0)        (K'=192)
    gemm_bfa<96, 6, true><<<dim3(8, 384), 256, smemA>>>(p_ac0, 192, p_w0i,
                                                        tb0, p_ac1, nullptr);
    // feats = act(h1' @ w1i'^T + b1)         (K'=768)
    gemm_bfa<96, 6, true><<<dim3(8, 384), 256, smemA>>>(p_ac1, 768, p_w1i,
                                                        tb1, p_ac2, nullptr);
    // g_xw = feats' @ w2c'^T                 (K'=768, raw gates for the scan)
    gemm_bfa<128, 8, false><<<dim3(4, 384), 256, smemR>>>(p_ac2, 768, p_w2c,
                                                          nullptr, nullptr, p_xw);

    const int smemS = 32896 * (int)sizeof(float);  // 131584 B
    cudaFuncSetAttribute(scan_kernel, cudaFuncAttributeMaxDynamicSharedMemorySize, smemS);
    scan_kernel<<<128, 256, smemS>>>(targets, nWhh0, nb0, nWih1, nWhh1, nb1,
                                     outW, outb, out);
}

// round 15
// speedup vs baseline: 1.2229x; 1.0026x over previous
#include <cuda_runtime.h>
#include <cuda_bf16.h>
#include <math.h>

// ---------------------------------------------------------------------------
// DeepJ biaxial LSTM.  B=1024, N=48, TU=256, NU=128, IN_T=50 (pad 64).
//   - time-axis layers: feed-forward gate GEMMs on mma.sync m16n8k16 bf16
//     with 3xK hi/lo split + fused activation epilogue.  NOW staged via a
//     cp.async 3-buffer ring (1 barrier/chunk, no register round-trip).
//   - note-axis scan: persistent scalar fp32, 256 threads, 128 blocks x 8
//     batches.  NOW: layer-1 fused into ONE pass over concatenated
//     [h1|h2] x [Wih1|Whh1] (K=256), and a CONTINUOUS cp.async tile stream
//     across pass/step boundaries (zero pipeline refill bubbles).
// ---------------------------------------------------------------------------

#define BB 1024
#define NN 48
#define MM (BB * NN)   // 49152

typedef __nv_bfloat16 bf16;

// scratch (device globals: allocation-free)
__device__ __align__(16) bf16  g_ac0[MM * 192];   // rnn_in split-concat (K'=192)
__device__ __align__(16) bf16  g_ac1[MM * 768];   // h1 split-concat     (K'=768)
__device__ __align__(16) bf16  g_ac2[MM * 768];   // feats split-concat  (K'=768)
__device__ __align__(16) bf16  g_w0i[768 * 192];  // t_Wih0 interleaved split-concat
__device__ __align__(16) bf16  g_w1i[768 * 768];  // t_Wih1 interleaved split-concat
__device__ __align__(16) bf16  g_w2c[512 * 768];  // n_Wih0[:, :256] split-concat
__device__ float g_wc[512];                       // n_Wih0[:, 256] (cond column)
__device__ __align__(16) float g_xw[MM * 512];    // raw gates for the scan
__device__ __align__(16) float g_wcat[512 * 256]; // [Wih1 | Whh1] concat (scan)

__device__ __forceinline__ float sigf(float x) {
    return __fdividef(1.0f, 1.0f + __expf(-x));
}

__device__ __forceinline__ void mma16(float c[4], const unsigned a[4],
                                      const unsigned b[2]) {
    asm volatile(
        "mma.sync.aligned.m16n8k16.row.col.f32.bf16.bf16.f32 "
        "{%0,%1,%2,%3}, {%4,%5,%6,%7}, {%8,%9}, {%0,%1,%2,%3};"
        : "+f"(c[0]), "+f"(c[1]), "+f"(c[2]), "+f"(c[3])
        : "r"(a[0]), "r"(a[1]), "r"(a[2]), "r"(a[3]), "r"(b[0]), "r"(b[1]));
}

static __device__ __forceinline__ unsigned smem_u32(const void* p) {
    unsigned a;
    asm("{ .reg .u64 t; cvta.to.shared.u64 t, %1; cvt.u32.u64 %0, t; }"
        : "=r"(a) : "l"(p));
    return a;
}
__device__ __forceinline__ void cp16(unsigned dst, const void* src) {
    asm volatile("cp.async.cg.shared.global [%0], [%1], 16;"
                 :: "r"(dst), "l"(src) : "memory");
}
template <int N>
__device__ __forceinline__ void cpwait() {
    asm volatile("cp.async.wait_group %0;" :: "n"(N) : "memory");
}
__device__ __forceinline__ void cpcommit() {
    asm volatile("cp.async.commit_group;" ::: "memory");
}

// ----------------------------- prep kernels -------------------------------

__device__ __forceinline__ void split3(float v, bf16* p0, bf16* p1, bf16* p2) {
    bf16 hh = __float2bfloat16(v);
    bf16 hl = __float2bfloat16(v - __bfloat162float(hh));
    *p0 = hh; *p1 = hl; *p2 = hh;          // activations: [hi | lo | hi]
}
__device__ __forceinline__ void splitw(float v, bf16* p0, bf16* p1, bf16* p2) {
    bf16 hh = __float2bfloat16(v);
    bf16 hl = __float2bfloat16(v - __bfloat162float(hh));
    *p0 = hh; *p1 = hh; *p2 = hl;          // weights: [hi | hi | lo]
}

__global__ void build_ac0(const float* __restrict__ note) {
    int idx = blockIdx.x * blockDim.x + threadIdx.x;   // MM * 64
    if (idx >= MM * 64) return;
    int f = idx & 63;
    int m = idx >> 6;
    int b = m / NN, n = m % NN;
    float v = 0.0f;
    if (f == 0) {
        v = (float)n * (1.0f / (float)NN);
    } else if (f < 13) {
        v = ((f - 1) == (n % 12)) ? 1.0f : 0.0f;
    } else if (f < 38) {
        int p = n + (f - 13) - 12;
        v = (p >= 0 && p < NN) ? note[b * NN + p] : 0.0f;
    } else if (f < 50) {
        const float* nb = note + b * NN + (f - 38) * 4;
        v = nb[0] + nb[1] + nb[2] + nb[3];
    }
    size_t o = (size_t)m * 192 + f;
    split3(v, &g_ac0[o], &g_ac0[o + 64], &g_ac0[o + 128]);
}

__global__ void build_w0i(const float* __restrict__ w) {   // (1024 x 50)
    int idx = blockIdx.x * blockDim.x + threadIdx.x;       // 768 * 64
    if (idx >= 768 * 64) return;
    int k = idx & 63, r = idx >> 6;
    int u = r / 3, g3 = r - 3 * u;
    int ga = (g3 == 0) ? 0 : g3 + 1;
    float v = (k < 50) ? w[(size_t)(ga * 256 + u) * 50 + k] : 0.0f;
    size_t o = (size_t)r * 192 + k;
    splitw(v, &g_w0i[o], &g_w0i[o + 64], &g_w0i[o + 128]);
}

__global__ void build_w1i(const float* __restrict__ w) {   // (1024 x 256)
    int idx = blockIdx.x * blockDim.x + threadIdx.x;       // 768 * 256
    if (idx >= 768 * 256) return;
    int k = idx & 255, r = idx >> 8;
    int u = r / 3, g3 = r - 3 * u;
    int ga = (g3 == 0) ? 0 : g3 + 1;
    float v = w[(size_t)(ga * 256 + u) * 256 + k];
    size_t o = (size_t)r * 768 + k;
    splitw(v, &g_w1i[o], &g_w1i[o + 256], &g_w1i[o + 512]);
}

__global__ void build_w2c(const float* __restrict__ w) {   // n_Wih0 (512 x 257)
    int idx = blockIdx.x * blockDim.x + threadIdx.x;       // 512 * 256
    if (idx >= 512 * 256) return;
    int k = idx & 255, r = idx >> 8;
    float v = w[(size_t)r * 257 + k];
    size_t o = (size_t)r * 768 + k;
    splitw(v, &g_w2c[o], &g_w2c[o + 256], &g_w2c[o + 512]);
    if (k == 0) g_wc[r] = w[(size_t)r * 257 + 256];
}

// [Wih1 | Whh1] -> g_wcat (512 x 256)
__global__ void build_wcat(const float* __restrict__ wi,
                           const float* __restrict__ wh) {
    int idx = blockIdx.x * blockDim.x + threadIdx.x;       // 512 * 256
    if (idx >= 512 * 256) return;
    int k = idx & 255, r = idx >> 8;
    g_wcat[(size_t)r * 256 + k] =
        (k < 128) ? wi[(size_t)r * 128 + k] : wh[(size_t)r * 128 + (k - 128)];
}

// ------------------ bf16 mma.sync gate GEMM, fused activation --------------
// cp.async 3-stage ring staging; one barrier per 32-k chunk.
// Stage layout (bytes): A at +0 (128 rows x 80B), B at +10240 (NT rows x 80B).

template <int NT, int NI, bool ACT>
__global__ __launch_bounds__(256)
void gemm_bfa(const bf16* __restrict__ A, int Kp,
              const bf16* __restrict__ W,
              const float* __restrict__ bias,
              bf16* __restrict__ outb_, float* __restrict__ outf) {
    extern __shared__ char smem[];
    constexpr unsigned SSZ = (128 + NT) * 80u;
    const unsigned sm_u32 = smem_u32(smem);

    const int t = threadIdx.x;
    const int lane = t & 31, wid = t >> 5;
    const int wm = wid & 3, wn = wid >> 2;
    const int gid = lane >> 2, tid4 = lane & 3;
    const int m0 = blockIdx.y * 128;
    const int c0 = blockIdx.x * NT;

    float acc[2][NI][4];
#pragma unroll
    for (int mi = 0; mi < 2; mi++)
#pragma unroll
        for (int ni = 0; ni < NI; ni++)
#pragma unroll
            for (int q = 0; q < 4; q++) acc[mi][ni][q] = 0.0f;

    const int nchunks = Kp >> 5;

    // stage(s, kc): A 512 cp16 (2/thread) + B NT*4 cp16
    auto stage = [&](int s, int kc) {
        unsigned dst = sm_u32 + (unsigned)s * SSZ;
#pragma unroll
        for (int j = 0; j < 2; j++) {
            int lin = t + 256 * j;
            int r = lin >> 2, p = lin & 3;
            cp16(dst + (unsigned)(r * 80 + p * 16),
                 A + (size_t)(m0 + r) * Kp + kc * 32 + p * 8);
        }
#pragma unroll
        for (int j = 0; j < 2; j++) {
            int lin = t + 256 * j;
            if (lin < NT * 4) {
                int r = lin >> 2, p = lin & 3;
                cp16(dst + 10240u + (unsigned)(r * 80 + p * 16),
                     W + (size_t)(c0 + r) * Kp + kc * 32 + p * 8);
            }
        }
        cpcommit();
    };

    stage(0, 0);
    if (nchunks > 1) stage(1, 1);

    for (int kc = 0; kc < nchunks; kc++) {
        if (kc == nchunks - 1) cpwait<0>(); else cpwait<1>();
        __syncthreads();
        if (kc + 2 < nchunks) stage((kc + 2) % 3, kc + 2);

        const bf16* sA = (const bf16*)(smem + (kc % 3) * SSZ);
        const bf16* sB = (const bf16*)(smem + (kc % 3) * SSZ + 10240);
#pragma unroll
        for (int kh = 0; kh < 2; kh++) {
            const int kb = kh * 16;
            unsigned Af[2][4], Bf[NI][2];
#pragma unroll
            for (int mi = 0; mi < 2; mi++) {
                int r = wm * 32 + mi * 16 + gid;
                Af[mi][0] = *(const unsigned*)&sA[r * 40 + kb + tid4 * 2];
                Af[mi][1] = *(const unsigned*)&sA[(r + 8) * 40 + kb + tid4 * 2];
                Af[mi][2] = *(const unsigned*)&sA[r * 40 + kb + tid4 * 2 + 8];
                Af[mi][3] = *(const unsigned*)&sA[(r + 8) * 40 + kb + tid4 * 2 + 8];
            }
#pragma unroll
            for (int ni = 0; ni < NI; ni++) {
                int c = wn * (NT / 2) + ni * 8 + gid;
                Bf[ni][0] = *(const unsigned*)&sB[c * 40 + kb + tid4 * 2];
                Bf[ni][1] = *(const unsigned*)&sB[c * 40 + kb + tid4 * 2 + 8];
            }
#pragma unroll
            for (int mi = 0; mi < 2; mi++)
#pragma unroll
                for (int ni = 0; ni < NI; ni++)
                    mma16(acc[mi][ni], Af[mi], Bf[ni]);
        }
    }
    __syncthreads();   // staging region now reusable as dump

    float* sd = (float*)smem;
    const int NTS = NT + 4;
#pragma unroll
    for (int mi = 0; mi < 2; mi++)
#pragma unroll
        for (int ni = 0; ni < NI; ni++) {
            int r = wm * 32 + mi * 16 + gid;
            int c = wn * (NT / 2) + ni * 8 + tid4 * 2;
            sd[r * NTS + c]           = acc[mi][ni][0];
            sd[r * NTS + c + 1]       = acc[mi][ni][1];
            sd[(r + 8) * NTS + c]     = acc[mi][ni][2];
            sd[(r + 8) * NTS + c + 1] = acc[mi][ni][3];
        }
    __syncthreads();

    if constexpr (ACT) {
        const int ul = t & 31, mr = t >> 5;
        const int ug = blockIdx.x * 32 + ul;
        const float bi = bias[ug];
        const float bg = bias[2 * 256 + ug];
        const float bo = bias[3 * 256 + ug];
#pragma unroll
        for (int j = 0; j < 16; j++) {
            int m = mr + j * 8;
            float gi = sd[m * NTS + ul * 3 + 0] + bi;
            float gg = sd[m * NTS + ul * 3 + 1] + bg;
            float go = sd[m * NTS + ul * 3 + 2] + bo;
            float h = sigf(go) * tanhf(sigf(gi) * tanhf(gg));
            size_t o = (size_t)(m0 + m) * 768 + ug;
            split3(h, &outb_[o], &outb_[o + 256], &outb_[o + 512]);
        }
    } else {
#pragma unroll
        for (int j = 0; j < 16; j++) {
            int i = j * 256 + t;
            int r = i >> 5, c4 = i & 31;
            *(float4*)&outf[(size_t)(m0 + r) * 512 + c0 + c4 * 4] =
                *(float4*)&sd[r * NTS + c4 * 4];
        }
    }
}

// ------------------------------ note-axis scan -----------------------------
// 256 threads, 128 blocks x 8 batches, 4 batches/thread.
// Per step: pass A = Whh0 (8 tiles, hv = h1), pass B = Wcat (16 tiles,
// hv = [h1|h2]).  One continuous 24-tile/step cp.async stream across all
// pass and step boundaries (3-buffer ring, 1 barrier/tile).
// smem: sW 3x512x20 | sHc 8x256 | sWo 128  = 131584 B.

#define SCAN_TILES (NN * 24)   // 1152

__device__ __forceinline__ void issue_seq(int s, const float* __restrict__ Wh0,
                                          unsigned sW_u32, int t) {
    int local = s % 24;
    const float* W;
    int ldw, kt;
    if (local < 8) { W = Wh0;    ldw = 128; kt = local * 16; }
    else           { W = g_wcat; ldw = 256; kt = (local - 8) * 16; }
    unsigned dst = sW_u32 + (unsigned)(s % 3) * 40960u;
#pragma unroll
    for (int i = 0; i < 8; i++) {
        int lin = t + 256 * i;          // 512 rows x 4 float4
        int r = lin >> 2, k4 = lin & 3;
        cp16(dst + (unsigned)(r * 80 + k4 * 16), W + r * ldw + kt + k4 * 4);
    }
    cpcommit();
}

__device__ __forceinline__ void accum_tile(float acc[4][4], const float* sWt,
                                           const float* sHc, int kt, int u, int bp) {
#pragma unroll
    for (int kk = 0; kk < 16; kk += 4) {
        float4 wv[4];
#pragma unroll
        for (int g = 0; g < 4; g++)
            wv[g] = *(const float4*)&sWt[(g * 128 + u) * 20 + kk];
#pragma unroll
        for (int b = 0; b < 4; b++) {
            float4 hv = *(const float4*)&sHc[(bp * 4 + b) * 256 + kt + kk];
#pragma unroll
            for (int g = 0; g < 4; g++) {
                acc[b][g] += hv.x * wv[g].x;
                acc[b][g] += hv.y * wv[g].y;
                acc[b][g] += hv.z * wv[g].z;
                acc[b][g] += hv.w * wv[g].w;
            }
        }
    }
}

__global__ __launch_bounds__(256, 1)
void scan_kernel(const float* __restrict__ targets,
                 const float* __restrict__ Whh0,
                 const float* __restrict__ nb0,
                 const float* __restrict__ nb1,
                 const float* __restrict__ outW,
                 const float* __restrict__ outb,
                 float* __restrict__ out) {
    extern __shared__ float sh[];
    float* sW  = sh;              // 3 x 512 x 20 = 30720
    float* sHc = sh + 30720;      // 8 x 256  (cols 0-127 h1, 128-255 h2)
    float* sWo = sHc + 2048;      // 128
    const unsigned sW_u32 = smem_u32(sW);

    const int t = threadIdx.x;
    const int u = t & 127, bp = t >> 7;
    const int B0 = blockIdx.x * 8;

    if (t < 128) sWo[t] = outW[t];
    for (int i = t; i < 2048; i += 256) sHc[i] = 0.0f;

    float c1[4] = {0, 0, 0, 0}, c2[4] = {0, 0, 0, 0};
    float b0r[4], b1r[4], wcr[4];
#pragma unroll
    for (int g = 0; g < 4; g++) {
        b0r[g] = nb0[g * 128 + u];
        b1r[g] = nb1[g * 128 + u];
        wcr[g] = g_wc[g * 128 + u];
    }
    const float ob = outb[0];
    __syncthreads();

    issue_seq(0, Whh0, sW_u32, t);
    issue_seq(1, Whh0, sW_u32, t);

    int s = 0;
    for (int n = 0; n < NN; n++) {
        // ---- layer 0: gates = xw + b + cond*wc + h1_prev @ Whh0^T ----
        float acc[4][4];
#pragma unroll
        for (int b = 0; b < 4; b++) {
            int bg = B0 + bp * 4 + b;
            float cond = (n == 0) ? 0.0f : targets[bg * NN + n - 1];
            size_t m = (size_t)bg * NN + n;
#pragma unroll
            for (int g = 0; g < 4; g++)
                acc[b][g] = g_xw[m * 512 + g * 128 + u] + b0r[g] + cond * wcr[g];
        }
        for (int it = 0; it < 8; it++) {
            if (s == SCAN_TILES - 1) cpwait<0>(); else cpwait<1>();
            __syncthreads();
            if (s + 2 < SCAN_TILES) issue_seq(s + 2, Whh0, sW_u32, t);
            accum_tile(acc, sW + (s % 3) * 10240, sHc, it * 16, u, bp);
            s++;
        }
        __syncthreads();           // all reads of h1_prev done

        // pointwise L0 -> sHc cols 0..127
#pragma unroll
        for (int b = 0; b < 4; b++) {
            float cc = sigf(acc[b][1]) * c1[b] + sigf(acc[b][0]) * tanhf(acc[b][2]);
            c1[b] = cc;
            sHc[(bp * 4 + b) * 256 + u] = sigf(acc[b][3]) * tanhf(cc);
        }
        __syncthreads();

        // ---- layer 1 (fused): gates = [h1|h2_prev] @ [Wih1|Whh1]^T + b1 ----
        float acc2[4][4];
#pragma unroll
        for (int b = 0; b < 4; b++)
#pragma unroll
            for (int g = 0; g < 4; g++) acc2[b][g] = b1r[g];
        for (int it = 0; it < 16; it++) {
            if (s == SCAN_TILES - 1) cpwait<0>(); else cpwait<1>();
            __syncthreads();
            if (s + 2 < SCAN_TILES) issue_seq(s + 2, Whh0, sW_u32, t);
            accum_tile(acc2, sW + (s % 3) * 10240, sHc, it * 16, u, bp);
            s++;
        }
        __syncthreads();           // all reads of h2_prev done

        // pointwise L1 -> sHc cols 128..255
#pragma unroll
        for (int b = 0; b < 4; b++) {
            float cc = sigf(acc2[b][1]) * c2[b] + sigf(acc2[b][0]) * tanhf(acc2[b][2]);
            c2[b] = cc;
            sHc[(bp * 4 + b) * 256 + 128 + u] = sigf(acc2[b][3]) * tanhf(cc);
        }
        __syncthreads();

        // ---- output: warp w handles batch w ----
        int w = t >> 5, lane = t & 31;
        float p = 0.0f;
#pragma unroll
        for (int j = 0; j < 4; j++)
            p += sHc[w * 256 + 128 + lane + 32 * j] * sWo[lane + 32 * j];
#pragma unroll
        for (int off = 16; off; off >>= 1)
            p += __shfl_down_sync(0xffffffffu, p, off);
        if (lane == 0) out[(B0 + w) * NN + n] = sigf(p + ob);
        // next overwrite of sHc h2 happens after L1 barriers next step
    }
}

// --------------------------------- launch ---------------------------------

extern "C" void kernel_launch(void* const* d_in, const int* in_sizes, int n_in,
                              void* d_out, int out_size) {
    (void)in_sizes; (void)n_in; (void)out_size;
    const float* note    = (const float*)d_in[0];
    const float* targets = (const float*)d_in[1];
    const float* tWih0   = (const float*)d_in[2];
    const float* tb0     = (const float*)d_in[4];
    const float* tWih1   = (const float*)d_in[5];
    const float* tb1     = (const float*)d_in[7];
    const float* nWih0   = (const float*)d_in[8];
    const float* nWhh0   = (const float*)d_in[9];
    const float* nb0     = (const float*)d_in[10];
    const float* nWih1   = (const float*)d_in[11];
    const float* nWhh1   = (const float*)d_in[12];
    const float* nb1     = (const float*)d_in[13];
    const float* outW    = (const float*)d_in[14];
    const float* outb    = (const float*)d_in[15];
    float* out = (float*)d_out;

    bf16 *p_ac0, *p_ac1, *p_ac2, *p_w0i, *p_w1i, *p_w2c;
    float *p_xw;
    cudaGetSymbolAddress((void**)&p_ac0, g_ac0);
    cudaGetSymbolAddress((void**)&p_ac1, g_ac1);
    cudaGetSymbolAddress((void**)&p_ac2, g_ac2);
    cudaGetSymbolAddress((void**)&p_w0i, g_w0i);
    cudaGetSymbolAddress((void**)&p_w1i, g_w1i);
    cudaGetSymbolAddress((void**)&p_w2c, g_w2c);
    cudaGetSymbolAddress((void**)&p_xw,  g_xw);

    build_ac0<<<(MM * 64) / 256, 256>>>(note);
    build_w0i<<<(768 * 64) / 256, 256>>>(tWih0);
    build_w1i<<<(768 * 256) / 256, 256>>>(tWih1);
    build_w2c<<<(512 * 256) / 256, 256>>>(nWih0);
    build_wcat<<<(512 * 256) / 256, 256>>>(nWih1, nWhh1);

    const int smemA = 3 * (128 + 96) * 80;              // 53760 (> dump 51200)
    const int smemR = 128 * 132 * (int)sizeof(float);   // 67584 (> staging 61440)
    cudaFuncSetAttribute((const void*)gemm_bfa<96, 6, true>,
                         cudaFuncAttributeMaxDynamicSharedMemorySize, smemA);
    cudaFuncSetAttribute((const void*)gemm_bfa<128, 8, false>,
                         cudaFuncAttributeMaxDynamicSharedMemorySize, smemR);

    // h1 = act(rnn_in' @ w0i'^T + b0)        (K'=192)
    gemm_bfa<96, 6, true><<<dim3(8, 384), 256, smemA>>>(p_ac0, 192, p_w0i,
                                                        tb0, p_ac1, nullptr);
    // feats = act(h1' @ w1i'^T + b1)         (K'=768)
    gemm_bfa<96, 6, true><<<dim3(8, 384), 256, smemA>>>(p_ac1, 768, p_w1i,
                                                        tb1, p_ac2, nullptr);
    // g_xw = feats' @ w2c'^T                 (K'=768, raw gates for the scan)
    gemm_bfa<128, 8, false><<<dim3(4, 384), 256, smemR>>>(p_ac2, 768, p_w2c,
                                                          nullptr, nullptr, p_xw);

    const int smemS = 32896 * (int)sizeof(float);  // 131584 B
    cudaFuncSetAttribute(scan_kernel, cudaFuncAttributeMaxDynamicSharedMemorySize, smemS);
    scan_kernel<<<128, 256, smemS>>>(targets, nWhh0, nb0, nb1, outW, outb, out);
}